// round 13
// baseline (speedup 1.0000x reference)
#include <cuda_runtime.h>
#include <cstdint>

#define E_DIM 128
#define B_SZ  1024
#define T_SZ  200
#define GRID  296            // 2 CTAs per SM, persistent
#define NTHR  256

#define ROW_A 272            // 128 fp16 padded to 272B (ldmatrix conflict-free)

#define OFF_A    0           // 208*272 = 56576
#define OFF_STG  56576       // 2 x 25600 fp32 staging (50 rows each)
#define STG_SZ   25600
#define OFF_QAP  107776      // 256 f32 = 1024
#define OFF_RED  108800      // 416 f32 = 1664
#define SMEM_BYTES 110464    // x2 = 220928 <= 228KB/SM

// prep0 output: fragment-ordered folded weights (L2-resident in main)
__device__ float g_WkF[8192];      // [id*8+u]: (W0b-W0c) at fragment slot
__device__ float g_WdF[8192];      // [id*8+u]: W0d
__device__ float g_Wq [64 * 128];  // [h*128+e]: W0a+W0c

__device__ __forceinline__ uint32_t pkf16(float lo, float hi) {
    uint32_t r;
    asm("cvt.rn.f16x2.f32 %0, %1, %2;" : "=r"(r) : "f"(hi), "f"(lo));
    return r;
}
__device__ __forceinline__ uint32_t smem_u32(const void* p) {
    uint32_t a;
    asm("{ .reg .u64 t; cvta.to.shared.u64 t, %1; cvt.u32.u64 %0, t; }" : "=r"(a) : "l"(p));
    return a;
}
__device__ __forceinline__ void cp16(uint32_t dst, const float4* src) {
    asm volatile("cp.async.cg.shared.global [%0], [%1], 16;"
                 :: "r"(dst), "l"(__cvta_generic_to_global(src)) : "memory");
}
#define CP_COMMIT() asm volatile("cp.async.commit_group;" ::: "memory")
#define CP_WAIT(n)  asm volatile("cp.async.wait_group %0;" :: "n"(n) : "memory")

#define LDSM4(r, addr) \
    asm volatile("ldmatrix.sync.aligned.m8n8.x4.shared.b16 {%0,%1,%2,%3}, [%4];" \
        : "=r"((r)[0]), "=r"((r)[1]), "=r"((r)[2]), "=r"((r)[3]) : "r"(addr))

__device__ __forceinline__ void mma_f16(float* c, const uint32_t* a, uint32_t b0, uint32_t b1) {
    asm volatile("mma.sync.aligned.m16n8k16.row.col.f32.f16.f16.f32 "
        "{%0,%1,%2,%3}, {%4,%5,%6,%7}, {%8,%9}, {%0,%1,%2,%3};"
        : "+f"(c[0]), "+f"(c[1]), "+f"(c[2]), "+f"(c[3])
        : "r"(a[0]), "r"(a[1]), "r"(a[2]), "r"(a[3]), "r"(b0), "r"(b1));
}

// fold W0 once into fragment-ordered tables (16384 slots)
__global__ void prep0(const float* __restrict__ W0) {
    int idx = blockIdx.x * blockDim.x + threadIdx.x;
    if (idx < 8192) {
        int id = idx >> 3, u = idx & 7;
        int lane = id & 31, k2 = (id >> 5) & 3, nt = (id >> 7) & 3, ng = id >> 9;
        int h = ng * 32 + nt * 8 + (lane >> 2);
        int e = 32 * k2 + 2 * (lane & 3) + ((u >> 1) << 3) + (u & 1);  // {0,1,8,9,16,17,24,25}
        g_WkF[idx] = W0[(128 + e) * 64 + h] - W0[(256 + e) * 64 + h];
        g_WdF[idx] = W0[(384 + e) * 64 + h];
    } else {
        int i = idx - 8192;
        int h = i & 63, e = i >> 6;
        g_Wq[h * 128 + e] = W0[e * 64 + h] + W0[(256 + e) * 64 + h];
    }
}

__global__ void __launch_bounds__(NTHR, 2) lau_main(
    const float* __restrict__ keys, const float* __restrict__ query,
    const float* __restrict__ b0,   const float* __restrict__ W1,
    const float* __restrict__ b1,   float* __restrict__ out)
{
    extern __shared__ __align__(1024) char sm[];
    const uint32_t smb = smem_u32(sm);
    const int tid = threadIdx.x;
    const int bid = blockIdx.x;
    const int w = tid >> 5, lane = tid & 31;
    const int mg = w >> 1, ng = w & 1;          // 4 m-groups x 2 n-groups
    const int lq = lane >> 2, lr = lane & 3;
    const int h6 = tid & 63, grp = tid >> 6;
    float* sQap = (float*)(sm + OFF_QAP);
    float* sRed = (float*)(sm + OFF_RED);

    const int nb = (B_SZ - 1 - bid) / GRID + 1;      // batches for this CTA
    const int nchunks = 4 * nb;

    // prologue: batch-invariant constants, zero A tail, kick first 2 chunks
    float w1v[8], qb0[8];
    #pragma unroll
    for (int nt = 0; nt < 4; nt++) {
        #pragma unroll
        for (int u = 0; u < 2; u++) {
            int c = ng * 32 + nt * 8 + 2 * lr + u;
            w1v[2 * nt + u] = __ldg(&W1[c]);
            qb0[2 * nt + u] = __ldg(&b0[c]);
        }
    }
    const float b1v = __ldg(b1);
    if (tid < 136)
        *(uint4*)(sm + OFF_A + 200 * ROW_A + tid * 16) = make_uint4(0, 0, 0, 0);

    #pragma unroll
    for (int s = 0; s < 2; s++) {                    // seq 0, 1
        const float4* src = (const float4*)(keys + ((size_t)bid * T_SZ + s * 50) * E_DIM);
        uint32_t stg = smb + OFF_STG + (s & 1) * STG_SZ;
        #pragma unroll
        for (int i = 0; i < 7; i++) {
            int idx = i * NTHR + tid;
            if (idx < 1600) cp16(stg + idx * 16, src + idx);
        }
        CP_COMMIT();
    }

    int j = 0;
    for (int b = bid; b < B_SZ; b += GRID, j++) {
        const float* qb = query + (size_t)b * E_DIM;

        // ---- B fragments in registers (L2-hot tables; overlaps chunk DRAM) ----
        uint32_t bf[4][8][2];
        #pragma unroll
        for (int nt = 0; nt < 4; nt++)
            #pragma unroll
            for (int k2 = 0; k2 < 4; k2++) {
                int id = ng * 512 + nt * 128 + k2 * 32 + lane;
                float4 wk0 = __ldg((const float4*)(g_WkF + id * 8));
                float4 wk1 = __ldg((const float4*)(g_WkF + id * 8 + 4));
                float4 wd0 = __ldg((const float4*)(g_WdF + id * 8));
                float4 wd1 = __ldg((const float4*)(g_WdF + id * 8 + 4));
                int e0 = 32 * k2 + 2 * (lane & 3);
                float2 q0 = __ldg((const float2*)(qb + e0));
                float2 q1 = __ldg((const float2*)(qb + e0 + 8));
                float2 q2 = __ldg((const float2*)(qb + e0 + 16));
                float2 q3 = __ldg((const float2*)(qb + e0 + 24));
                bf[nt][2*k2][0]   = pkf16(fmaf(q0.x, wd0.x, wk0.x), fmaf(q0.y, wd0.y, wk0.y));
                bf[nt][2*k2][1]   = pkf16(fmaf(q1.x, wd0.z, wk0.z), fmaf(q1.y, wd0.w, wk0.w));
                bf[nt][2*k2+1][0] = pkf16(fmaf(q2.x, wd1.x, wk1.x), fmaf(q2.y, wd1.y, wk1.y));
                bf[nt][2*k2+1][1] = pkf16(fmaf(q3.x, wd1.z, wk1.z), fmaf(q3.y, wd1.w, wk1.w));
            }

        // ---- qA partials: qap[grp][h] = sum_{e in grp slice} q[e]*Wq[e,h] ----
        {
            float pp = 0.f;
            #pragma unroll
            for (int i4 = 0; i4 < 8; i4++) {
                float4 wv = __ldg((const float4*)(g_Wq + h6 * 128 + grp * 32 + i4 * 4));
                float4 qv = __ldg((const float4*)(qb + grp * 32 + i4 * 4));
                pp += wv.x * qv.x + wv.y * qv.y + wv.z * qv.z + wv.w * qv.w;
            }
            sQap[grp * 64 + h6] = pp;
        }

        // ---- 4 chunk phases: wait, read, refill (cross-batch), convert ----
        #pragma unroll
        for (int c = 0; c < 4; c++) {
            const int s = 4 * j + c;
            CP_WAIT(1);
            const float4* s4 = (const float4*)(sm + OFF_STG + (s & 1) * STG_SZ);
            float4 v[7];
            #pragma unroll
            for (int i = 0; i < 7; i++) {
                int idx = i * NTHR + tid;
                if (idx < 1600) v[i] = s4[idx];
            }
            const int s2 = s + 2;
            if (s2 < nchunks) {
                int b2 = bid + (s2 >> 2) * GRID;
                const float4* src = (const float4*)(keys + ((size_t)b2 * T_SZ + (s2 & 3) * 50) * E_DIM);
                uint32_t stg = smb + OFF_STG + (s2 & 1) * STG_SZ;
                #pragma unroll
                for (int i = 0; i < 7; i++) {
                    int idx = i * NTHR + tid;
                    if (idx < 1600) cp16(stg + idx * 16, src + idx);
                }
            }
            CP_COMMIT();
            #pragma unroll
            for (int i = 0; i < 7; i++) {
                int idx = i * NTHR + tid;
                if (idx < 1600) {
                    int row = c * 50 + (idx >> 5), cc = idx & 31;
                    *(uint2*)(sm + OFF_A + row * ROW_A + cc * 8) =
                        make_uint2(pkf16(v[i].x, v[i].y), pkf16(v[i].z, v[i].w));
                }
            }
        }
        __syncthreads();                             // (1) A + qap ready

        // per-thread qa for this batch
        float qa[8];
        #pragma unroll
        for (int nt = 0; nt < 4; nt++) {
            #pragma unroll
            for (int u = 0; u < 2; u++) {
                int c = ng * 32 + nt * 8 + 2 * lr + u;
                qa[2 * nt + u] = qb0[2 * nt + u] + sQap[c] + sQap[64 + c]
                               + sQap[128 + c] + sQap[192 + c];
            }
        }

        // ---- per-tile mma + inline epilogue ----
        const uint32_t aB = smb + OFF_A + (lane & 15) * ROW_A + (lane >> 4) * 16;
        #pragma unroll
        for (int i = 0; i < 4; i++) {
            int t = mg + 4 * i;
            if (t < 13) {
                float acc[4][4];
                #pragma unroll
                for (int nt = 0; nt < 4; nt++)
                    #pragma unroll
                    for (int u = 0; u < 4; u++) acc[nt][u] = 0.f;
                #pragma unroll
                for (int ks = 0; ks < 8; ks++) {
                    uint32_t a[4];
                    LDSM4(a, aB + t * (16 * ROW_A) + ks * 32);
                    #pragma unroll
                    for (int nt = 0; nt < 4; nt++)
                        mma_f16(acc[nt], a, bf[nt][ks][0], bf[nt][ks][1]);
                }
                float p0 = 0.f, p1 = 0.f;
                #pragma unroll
                for (int nt = 0; nt < 4; nt++) {
                    p0 += fmaxf(acc[nt][0] + qa[2 * nt],     0.f) * w1v[2 * nt]
                        + fmaxf(acc[nt][1] + qa[2 * nt + 1], 0.f) * w1v[2 * nt + 1];
                    p1 += fmaxf(acc[nt][2] + qa[2 * nt],     0.f) * w1v[2 * nt]
                        + fmaxf(acc[nt][3] + qa[2 * nt + 1], 0.f) * w1v[2 * nt + 1];
                }
                p0 += __shfl_xor_sync(0xffffffffu, p0, 1);
                p0 += __shfl_xor_sync(0xffffffffu, p0, 2);
                p1 += __shfl_xor_sync(0xffffffffu, p1, 1);
                p1 += __shfl_xor_sync(0xffffffffu, p1, 2);
                if (lr == 0) {
                    sRed[ng * 208 + t * 16 + lq]     = p0;
                    sRed[ng * 208 + t * 16 + lq + 8] = p1;
                }
            }
        }
        __syncthreads();                             // (2) sRed ready
        if (tid < T_SZ)
            out[(size_t)b * T_SZ + tid] = sRed[tid] + sRed[208 + tid] + b1v;
        // next batch's sync (1) orders A/sQap/sRed reuse
    }
}

extern "C" void kernel_launch(void* const* d_in, const int* in_sizes, int n_in,
                              void* d_out, int out_size) {
    const float* query = (const float*)d_in[0];
    const float* keys  = (const float*)d_in[1];
    const float* W0    = (const float*)d_in[2];
    const float* b0    = (const float*)d_in[3];
    const float* W1    = (const float*)d_in[4];
    const float* b1    = (const float*)d_in[5];
    float* out = (float*)d_out;

    cudaFuncSetAttribute(lau_main, cudaFuncAttributeMaxDynamicSharedMemorySize, SMEM_BYTES);

    prep0<<<64, 256>>>(W0);
    lau_main<<<GRID, NTHR, SMEM_BYTES>>>(keys, query, b0, W1, b1, out);
}

// round 14
// speedup vs baseline: 1.3933x; 1.3933x over previous
#include <cuda_runtime.h>
#include <cstdint>

#define E_DIM 128
#define B_SZ  1024
#define T_SZ  200
#define GRID  296
#define NTHR  256

#define ROW_A 272            // 128 fp16 padded to 272B (ldmatrix conflict-free)
#define ROW_W 132

#define OFF_A    0           // 208*272 = 56576
#define OFF_STG  56576       // 2 x 25600 fp32 staging (50 rows each)
#define STG_SZ   25600
#define OFF_RED  107776      // 416 f32 = 1664
#define SMEM_BYTES 109440    // x2 CTAs/SM = 218880 <= 228KB

#define PREP1_SMEM 102912

// device scratch
__device__ float g_Wk[64 * 128];        // folded W0b-W0c   [h*128+e]
__device__ float g_Wd[64 * 128];        // W0d              [h*128+e]
__device__ float g_Wq[64 * 128];        // W0a+W0c          [h*128+e]
__device__ uint4 g_Wbf[B_SZ * 1024];    // per-batch B fragments [b][ng][nt][k2][lane]
__device__ float g_qA[B_SZ * 64];       // b0 folded in

__device__ __forceinline__ uint32_t pkf16(float lo, float hi) {
    uint32_t r;
    asm("cvt.rn.f16x2.f32 %0, %1, %2;" : "=r"(r) : "f"(hi), "f"(lo));
    return r;
}
__device__ __forceinline__ uint32_t smem_u32(const void* p) {
    uint32_t a;
    asm("{ .reg .u64 t; cvta.to.shared.u64 t, %1; cvt.u32.u64 %0, t; }" : "=r"(a) : "l"(p));
    return a;
}
__device__ __forceinline__ void cp16(uint32_t dst, const float4* src) {
    asm volatile("cp.async.cg.shared.global [%0], [%1], 16;"
                 :: "r"(dst), "l"(__cvta_generic_to_global(src)) : "memory");
}
#define CP_COMMIT() asm volatile("cp.async.commit_group;" ::: "memory")
#define CP_WAIT(n)  asm volatile("cp.async.wait_group %0;" :: "n"(n) : "memory")

#define LDSM4(r, addr) \
    asm volatile("ldmatrix.sync.aligned.m8n8.x4.shared.b16 {%0,%1,%2,%3}, [%4];" \
        : "=r"((r)[0]), "=r"((r)[1]), "=r"((r)[2]), "=r"((r)[3]) : "r"(addr))

__device__ __forceinline__ void mma_f16(float* c, const uint32_t* a, uint32_t b0, uint32_t b1) {
    asm volatile("mma.sync.aligned.m16n8k16.row.col.f32.f16.f16.f32 "
        "{%0,%1,%2,%3}, {%4,%5,%6,%7}, {%8,%9}, {%0,%1,%2,%3};"
        : "+f"(c[0]), "+f"(c[1]), "+f"(c[2]), "+f"(c[3])
        : "r"(a[0]), "r"(a[1]), "r"(a[2]), "r"(a[3]), "r"(b0), "r"(b1));
}

// ---- prep0: fold W0 once ----
__global__ void prep0(const float* __restrict__ W0) {
    int idx = blockIdx.x * blockDim.x + threadIdx.x;   // 8192
    int h = idx & 63, e = idx >> 6;
    float wa = W0[e * 64 + h];
    float wb = W0[(128 + e) * 64 + h];
    float wc = W0[(256 + e) * 64 + h];
    float wd = W0[(384 + e) * 64 + h];
    g_Wk[h * 128 + e] = wb - wc;
    g_Wd[h * 128 + e] = wd;
    g_Wq[h * 128 + e] = wa + wc;
}

// ---- prep1: per-batch W_b fragments + qA; 4 batches per block, grid 256 ----
__global__ void __launch_bounds__(256, 1) prep1(
    const float* __restrict__ query, const float* __restrict__ b0)
{
    extern __shared__ float ps[];
    float* sWk = ps;
    float* sWd = ps + 64 * ROW_W;
    float* sWq = ps + 2 * 64 * ROW_W;
    float* sq  = ps + 3 * 64 * ROW_W;
    float* sr  = sq + 128;
    const int tid = threadIdx.x;

    for (int idx = tid; idx < 8192; idx += 256) {
        int h = idx & 63, e = idx >> 6;
        sWk[h * ROW_W + e] = g_Wk[h * 128 + e];
        sWd[h * ROW_W + e] = g_Wd[h * 128 + e];
        sWq[h * ROW_W + e] = g_Wq[h * 128 + e];
    }
    __syncthreads();

    for (int bi = 0; bi < 4; bi++) {
        const int b = blockIdx.x * 4 + bi;
        if (tid < 128) sq[tid] = query[(size_t)b * E_DIM + tid];
        __syncthreads();

        #pragma unroll
        for (int j = 0; j < 4; j++) {
            int id = j * 256 + tid;
            int lane = id & 31, k2 = (id >> 5) & 3, nt = (id >> 7) & 3, ng = id >> 9;
            int n = lane >> 2, kc = 2 * (lane & 3);
            int h = ng * 32 + nt * 8 + n;
            int e0 = 32 * k2 + kc, e1 = e0 + 16;
            const float* wk = sWk + h * ROW_W;
            const float* wd = sWd + h * ROW_W;
            uint4 v;
            v.x = pkf16(fmaf(sq[e0],     wd[e0],     wk[e0]),
                        fmaf(sq[e0 + 1], wd[e0 + 1], wk[e0 + 1]));
            v.y = pkf16(fmaf(sq[e0 + 8], wd[e0 + 8], wk[e0 + 8]),
                        fmaf(sq[e0 + 9], wd[e0 + 9], wk[e0 + 9]));
            v.z = pkf16(fmaf(sq[e1],     wd[e1],     wk[e1]),
                        fmaf(sq[e1 + 1], wd[e1 + 1], wk[e1 + 1]));
            v.w = pkf16(fmaf(sq[e1 + 8], wd[e1 + 8], wk[e1 + 8]),
                        fmaf(sq[e1 + 9], wd[e1 + 9], wk[e1 + 9]));
            g_Wbf[(size_t)b * 1024 + id] = v;
        }
        {
            int h = tid & 63, grp = tid >> 6;
            float p = 0.f;
            #pragma unroll 8
            for (int i = 0; i < 32; i++) {
                int e = grp * 32 + i;
                p += sq[e] * sWq[h * ROW_W + e];
            }
            sr[grp * 64 + h] = p;
        }
        __syncthreads();
        if (tid < 64)
            g_qA[(size_t)b * 64 + tid] = b0[tid] + sr[tid] + sr[64 + tid]
                                       + sr[128 + tid] + sr[192 + tid];
        __syncthreads();
    }
}

// ---- main: persistent, split-half mma overlaps DRAM streaming ----
__global__ void __launch_bounds__(NTHR, 2) lau_main(
    const float* __restrict__ keys, const float* __restrict__ W1,
    const float* __restrict__ b1,   float* __restrict__ out)
{
    extern __shared__ __align__(1024) char sm[];
    const uint32_t smb = smem_u32(sm);
    const int tid = threadIdx.x;
    const int bid = blockIdx.x;
    const int w = tid >> 5, lane = tid & 31;
    const int mg = w >> 1, ng = w & 1;
    const int lq = lane >> 2, lr = lane & 3;
    float* sRed = (float*)(sm + OFF_RED);

    const int nb = (B_SZ - 1 - bid) / GRID + 1;
    const int nchunks = 4 * nb;

    float w1v[8];
    #pragma unroll
    for (int nt = 0; nt < 4; nt++) {
        w1v[2 * nt]     = __ldg(&W1[ng * 32 + nt * 8 + 2 * lr]);
        w1v[2 * nt + 1] = __ldg(&W1[ng * 32 + nt * 8 + 2 * lr + 1]);
    }
    const float b1v = __ldg(b1);
    if (tid < 136)
        *(uint4*)(sm + OFF_A + 200 * ROW_A + tid * 16) = make_uint4(0, 0, 0, 0);

    #pragma unroll
    for (int s = 0; s < 2; s++) {
        const float4* src = (const float4*)(keys + ((size_t)bid * T_SZ + s * 50) * E_DIM);
        uint32_t stg = smb + OFF_STG + (s & 1) * STG_SZ;
        #pragma unroll
        for (int i = 0; i < 7; i++) {
            int idx = i * NTHR + tid;
            if (idx < 1600) cp16(stg + idx * 16, src + idx);
        }
        CP_COMMIT();
    }

    const uint32_t aB = smb + OFF_A + (lane & 15) * ROW_A + (lane >> 4) * 16;

    int j = 0;
    for (int b = bid; b < B_SZ; b += GRID, j++) {
        // B fragments (coalesced, L2-resident after prep1)
        uint32_t bf[4][8][2];
        {
            const uint4* wb4 = g_Wbf + ((size_t)b * 2 + ng) * 512 + lane;
            #pragma unroll
            for (int nt = 0; nt < 4; nt++)
                #pragma unroll
                for (int k2 = 0; k2 < 4; k2++) {
                    uint4 v = __ldg(&wb4[nt * 128 + k2 * 32]);
                    bf[nt][2 * k2][0] = v.x;     bf[nt][2 * k2][1] = v.y;
                    bf[nt][2 * k2 + 1][0] = v.z; bf[nt][2 * k2 + 1][1] = v.w;
                }
        }
        float qa[8];
        #pragma unroll
        for (int nt = 0; nt < 4; nt++) {
            qa[2 * nt]     = __ldg(&g_qA[(size_t)b * 64 + ng * 32 + nt * 8 + 2 * lr]);
            qa[2 * nt + 1] = __ldg(&g_qA[(size_t)b * 64 + ng * 32 + nt * 8 + 2 * lr + 1]);
        }

        float acc[2][4][4];

        // ---- chunk phases 0,1: rows 0-99 ----
        #pragma unroll
        for (int c = 0; c < 2; c++) {
            const int s = 4 * j + c;
            CP_WAIT(1);
            const float4* s4 = (const float4*)(sm + OFF_STG + (s & 1) * STG_SZ);
            float4 v[7];
            #pragma unroll
            for (int i = 0; i < 7; i++) {
                int idx = i * NTHR + tid;
                if (idx < 1600) v[i] = s4[idx];
            }
            const int s2 = s + 2;
            if (s2 < nchunks) {
                int b2 = bid + (s2 >> 2) * GRID;
                const float4* src = (const float4*)(keys + ((size_t)b2 * T_SZ + (s2 & 3) * 50) * E_DIM);
                uint32_t stg = smb + OFF_STG + (s2 & 1) * STG_SZ;
                #pragma unroll
                for (int i = 0; i < 7; i++) {
                    int idx = i * NTHR + tid;
                    if (idx < 1600) cp16(stg + idx * 16, src + idx);
                }
            }
            CP_COMMIT();
            #pragma unroll
            for (int i = 0; i < 7; i++) {
                int idx = i * NTHR + tid;
                if (idx < 1600) {
                    int row = c * 50 + (idx >> 5), cc = idx & 31;
                    *(uint2*)(sm + OFF_A + row * ROW_A + cc * 8) =
                        make_uint2(pkf16(v[i].x, v[i].y), pkf16(v[i].z, v[i].w));
                }
            }
        }
        __syncthreads();                         // (S1) rows 0-99 ready

        // ---- first-half mma: tiles 0-5 (rows 0-95); chunks 2,3 stream behind ----
        #pragma unroll
        for (int i = 0; i < 2; i++) {
            int t = mg + 4 * i;                  // 0..7 -> first half if t < 6
            if (t < 6) {
                #pragma unroll
                for (int nt = 0; nt < 4; nt++)
                    #pragma unroll
                    for (int u = 0; u < 4; u++) acc[i][nt][u] = 0.f;
                #pragma unroll
                for (int ks = 0; ks < 8; ks++) {
                    uint32_t a[4];
                    LDSM4(a, aB + t * (16 * ROW_A) + ks * 32);
                    #pragma unroll
                    for (int nt = 0; nt < 4; nt++)
                        mma_f16(acc[i][nt], a, bf[nt][ks][0], bf[nt][ks][1]);
                }
                float p0 = 0.f, p1 = 0.f;
                #pragma unroll
                for (int nt = 0; nt < 4; nt++) {
                    p0 += fmaxf(acc[i][nt][0] + qa[2 * nt],     0.f) * w1v[2 * nt]
                        + fmaxf(acc[i][nt][1] + qa[2 * nt + 1], 0.f) * w1v[2 * nt + 1];
                    p1 += fmaxf(acc[i][nt][2] + qa[2 * nt],     0.f) * w1v[2 * nt]
                        + fmaxf(acc[i][nt][3] + qa[2 * nt + 1], 0.f) * w1v[2 * nt + 1];
                }
                p0 += __shfl_xor_sync(0xffffffffu, p0, 1);
                p0 += __shfl_xor_sync(0xffffffffu, p0, 2);
                p1 += __shfl_xor_sync(0xffffffffu, p1, 1);
                p1 += __shfl_xor_sync(0xffffffffu, p1, 2);
                if (lr == 0) {
                    sRed[ng * 208 + t * 16 + lq]     = p0;
                    sRed[ng * 208 + t * 16 + lq + 8] = p1;
                }
            }
        }

        // ---- chunk phases 2,3: rows 100-199 ----
        #pragma unroll
        for (int c = 2; c < 4; c++) {
            const int s = 4 * j + c;
            CP_WAIT(1);
            const float4* s4 = (const float4*)(sm + OFF_STG + (s & 1) * STG_SZ);
            float4 v[7];
            #pragma unroll
            for (int i = 0; i < 7; i++) {
                int idx = i * NTHR + tid;
                if (idx < 1600) v[i] = s4[idx];
            }
            const int s2 = s + 2;
            if (s2 < nchunks) {
                int b2 = bid + (s2 >> 2) * GRID;
                const float4* src = (const float4*)(keys + ((size_t)b2 * T_SZ + (s2 & 3) * 50) * E_DIM);
                uint32_t stg = smb + OFF_STG + (s2 & 1) * STG_SZ;
                #pragma unroll
                for (int i = 0; i < 7; i++) {
                    int idx = i * NTHR + tid;
                    if (idx < 1600) cp16(stg + idx * 16, src + idx);
                }
            }
            CP_COMMIT();
            #pragma unroll
            for (int i = 0; i < 7; i++) {
                int idx = i * NTHR + tid;
                if (idx < 1600) {
                    int row = c * 50 + (idx >> 5), cc = idx & 31;
                    *(uint2*)(sm + OFF_A + row * ROW_A + cc * 8) =
                        make_uint2(pkf16(v[i].x, v[i].y), pkf16(v[i].z, v[i].w));
                }
            }
        }
        __syncthreads();                         // (S2) rows 100-199 ready

        // ---- second-half mma: tiles 6-12 ----
        #pragma unroll
        for (int i = 0; i < 4; i++) {
            int t = mg + 4 * i;
            if (t >= 6 && t < 13) {
                int ii = i & 1;
                #pragma unroll
                for (int nt = 0; nt < 4; nt++)
                    #pragma unroll
                    for (int u = 0; u < 4; u++) acc[ii][nt][u] = 0.f;
                #pragma unroll
                for (int ks = 0; ks < 8; ks++) {
                    uint32_t a[4];
                    LDSM4(a, aB + t * (16 * ROW_A) + ks * 32);
                    #pragma unroll
                    for (int nt = 0; nt < 4; nt++)
                        mma_f16(acc[ii][nt], a, bf[nt][ks][0], bf[nt][ks][1]);
                }
                float p0 = 0.f, p1 = 0.f;
                #pragma unroll
                for (int nt = 0; nt < 4; nt++) {
                    p0 += fmaxf(acc[ii][nt][0] + qa[2 * nt],     0.f) * w1v[2 * nt]
                        + fmaxf(acc[ii][nt][1] + qa[2 * nt + 1], 0.f) * w1v[2 * nt + 1];
                    p1 += fmaxf(acc[ii][nt][2] + qa[2 * nt],     0.f) * w1v[2 * nt]
                        + fmaxf(acc[ii][nt][3] + qa[2 * nt + 1], 0.f) * w1v[2 * nt + 1];
                }
                p0 += __shfl_xor_sync(0xffffffffu, p0, 1);
                p0 += __shfl_xor_sync(0xffffffffu, p0, 2);
                p1 += __shfl_xor_sync(0xffffffffu, p1, 1);
                p1 += __shfl_xor_sync(0xffffffffu, p1, 2);
                if (lr == 0) {
                    sRed[ng * 208 + t * 16 + lq]     = p0;
                    sRed[ng * 208 + t * 16 + lq + 8] = p1;
                }
            }
        }
        __syncthreads();                         // (S3) sRed ready
        if (tid < T_SZ)
            out[(size_t)b * T_SZ + tid] = sRed[tid] + sRed[208 + tid] + b1v;
        // next batch's S1 orders A/sRed reuse
    }
}

extern "C" void kernel_launch(void* const* d_in, const int* in_sizes, int n_in,
                              void* d_out, int out_size) {
    const float* query = (const float*)d_in[0];
    const float* keys  = (const float*)d_in[1];
    const float* W0    = (const float*)d_in[2];
    const float* b0    = (const float*)d_in[3];
    const float* W1    = (const float*)d_in[4];
    const float* b1    = (const float*)d_in[5];
    float* out = (float*)d_out;

    cudaFuncSetAttribute(prep1, cudaFuncAttributeMaxDynamicSharedMemorySize, PREP1_SMEM);
    cudaFuncSetAttribute(lau_main, cudaFuncAttributeMaxDynamicSharedMemorySize, SMEM_BYTES);

    prep0<<<32, 256>>>(W0);
    prep1<<<256, 256, PREP1_SMEM>>>(query, b0);
    lau_main<<<GRID, NTHR, SMEM_BYTES>>>(keys, W1, b1, out);
}

// round 15
// speedup vs baseline: 2.3835x; 1.7106x over previous
#include <cuda_runtime.h>
#include <cstdint>

#define E_DIM 128
#define B_SZ  1024
#define T_SZ  200
#define GRID  296
#define NTHR  256

#define ROW_A 272            // 128 fp16 padded to 272B (ldmatrix conflict-free)

#define OFF_A    0           // 208*272 = 56576
#define OFF_STG  56576       // 2 x 25600 fp32 staging (50 rows each)
#define STG_SZ   25600
#define OFF_RED  107776      // 416 f32 = 1664
#define SMEM_BYTES 109440    // x2 CTAs/SM = 218880 <= 228KB

// device scratch
__device__ float g_WkF[8192];           // fragment-ordered W0b-W0c
__device__ float g_WdF[8192];           // fragment-ordered W0d
__device__ float g_WqT[128 * 64];       // [e*64+h] W0a+W0c (coalesced for qA)
__device__ uint4 g_Wbf[B_SZ * 1024];    // per-batch B fragments [b][ng][nt][k2][lane]
__device__ float g_qA[B_SZ * 64];       // b0 folded in

__device__ __forceinline__ uint32_t pkf16(float lo, float hi) {
    uint32_t r;
    asm("cvt.rn.f16x2.f32 %0, %1, %2;" : "=r"(r) : "f"(hi), "f"(lo));
    return r;
}
__device__ __forceinline__ uint32_t smem_u32(const void* p) {
    uint32_t a;
    asm("{ .reg .u64 t; cvta.to.shared.u64 t, %1; cvt.u32.u64 %0, t; }" : "=r"(a) : "l"(p));
    return a;
}
__device__ __forceinline__ void cp16(uint32_t dst, const float4* src) {
    asm volatile("cp.async.cg.shared.global [%0], [%1], 16;"
                 :: "r"(dst), "l"(__cvta_generic_to_global(src)) : "memory");
}
#define CP_COMMIT() asm volatile("cp.async.commit_group;" ::: "memory")
#define CP_WAIT(n)  asm volatile("cp.async.wait_group %0;" :: "n"(n) : "memory")

#define LDSM4(r, addr) \
    asm volatile("ldmatrix.sync.aligned.m8n8.x4.shared.b16 {%0,%1,%2,%3}, [%4];" \
        : "=r"((r)[0]), "=r"((r)[1]), "=r"((r)[2]), "=r"((r)[3]) : "r"(addr))

__device__ __forceinline__ void mma_f16(float* c, const uint32_t* a, uint32_t b0, uint32_t b1) {
    asm volatile("mma.sync.aligned.m16n8k16.row.col.f32.f16.f16.f32 "
        "{%0,%1,%2,%3}, {%4,%5,%6,%7}, {%8,%9}, {%0,%1,%2,%3};"
        : "+f"(c[0]), "+f"(c[1]), "+f"(c[2]), "+f"(c[3])
        : "r"(a[0]), "r"(a[1]), "r"(a[2]), "r"(a[3]), "r"(b0), "r"(b1));
}

// ---- prep0: fold W0 into fragment-ordered tables (grid 64 x 256) ----
__global__ void prep0(const float* __restrict__ W0) {
    int idx = blockIdx.x * blockDim.x + threadIdx.x;
    if (idx < 8192) {
        int id = idx >> 3, u = idx & 7;
        int lane = id & 31, k2 = (id >> 5) & 3, nt = (id >> 7) & 3, ng = id >> 9;
        int h = ng * 32 + nt * 8 + (lane >> 2);
        int e = 32 * k2 + 2 * (lane & 3) + ((u >> 1) << 3) + (u & 1);  // {0,1,8,9,16,17,24,25}
        g_WkF[idx] = __ldg(&W0[(128 + e) * 64 + h]) - __ldg(&W0[(256 + e) * 64 + h]);
        g_WdF[idx] = __ldg(&W0[(384 + e) * 64 + h]);
    } else {
        int i = idx - 8192;
        int h = i & 63, e = i >> 6;
        g_WqT[e * 64 + h] = __ldg(&W0[e * 64 + h]) + __ldg(&W0[(256 + e) * 64 + h]);
    }
}

// ---- prep1: per-batch B fragments + qA; 1 batch per block, grid 1024 ----
__global__ void __launch_bounds__(256, 4) prep1(
    const float* __restrict__ query, const float* __restrict__ b0)
{
    __shared__ float sq[128];
    __shared__ float sr[256];
    const int tid = threadIdx.x;
    const int b = blockIdx.x;

    if (tid < 128) sq[tid] = __ldg(&query[(size_t)b * E_DIM + tid]);
    __syncthreads();

    // B fragments (coalesced table reads, same mapping R12/R11 verified)
    #pragma unroll
    for (int j = 0; j < 4; j++) {
        int id = j * 256 + tid;
        int lane = id & 31, k2 = (id >> 5) & 3;
        int e0 = 32 * k2 + 2 * (lane & 3);
        float4 wk0 = __ldg((const float4*)(g_WkF + id * 8));
        float4 wk1 = __ldg((const float4*)(g_WkF + id * 8 + 4));
        float4 wd0 = __ldg((const float4*)(g_WdF + id * 8));
        float4 wd1 = __ldg((const float4*)(g_WdF + id * 8 + 4));
        uint4 v;
        v.x = pkf16(fmaf(sq[e0],      wd0.x, wk0.x), fmaf(sq[e0 + 1],  wd0.y, wk0.y));
        v.y = pkf16(fmaf(sq[e0 + 8],  wd0.z, wk0.z), fmaf(sq[e0 + 9],  wd0.w, wk0.w));
        v.z = pkf16(fmaf(sq[e0 + 16], wd1.x, wk1.x), fmaf(sq[e0 + 17], wd1.y, wk1.y));
        v.w = pkf16(fmaf(sq[e0 + 24], wd1.z, wk1.z), fmaf(sq[e0 + 25], wd1.w, wk1.w));
        g_Wbf[(size_t)b * 1024 + id] = v;
    }

    // qA partial (coalesced g_WqT reads)
    {
        int h6 = tid & 63, grp = tid >> 6;
        float p = 0.f;
        #pragma unroll 8
        for (int i = 0; i < 32; i++) {
            int e = grp * 32 + i;
            p += sq[e] * __ldg(&g_WqT[e * 64 + h6]);
        }
        sr[grp * 64 + h6] = p;
    }
    __syncthreads();
    if (tid < 64)
        g_qA[(size_t)b * 64 + tid] = __ldg(&b0[tid]) + sr[tid] + sr[64 + tid]
                                   + sr[128 + tid] + sr[192 + tid];
}

// ---- main: persistent, R11 inner loop + cross-batch cp.async pipeline ----
__global__ void __launch_bounds__(NTHR, 2) lau_main(
    const float* __restrict__ keys, const float* __restrict__ W1,
    const float* __restrict__ b1,   float* __restrict__ out)
{
    extern __shared__ __align__(1024) char sm[];
    const uint32_t smb = smem_u32(sm);
    const int tid = threadIdx.x;
    const int bid = blockIdx.x;
    const int w = tid >> 5, lane = tid & 31;
    const int mg = w >> 1, ng = w & 1;          // 4 m-groups x 2 n-groups
    const int lq = lane >> 2, lr = lane & 3;
    float* sRed = (float*)(sm + OFF_RED);

    const int nb = (B_SZ - 1 - bid) / GRID + 1;
    const int nchunks = 4 * nb;

    float w1v[8];
    #pragma unroll
    for (int nt = 0; nt < 4; nt++) {
        w1v[2 * nt]     = __ldg(&W1[ng * 32 + nt * 8 + 2 * lr]);
        w1v[2 * nt + 1] = __ldg(&W1[ng * 32 + nt * 8 + 2 * lr + 1]);
    }
    const float b1v = __ldg(b1);
    if (tid < 136)
        *(uint4*)(sm + OFF_A + 200 * ROW_A + tid * 16) = make_uint4(0, 0, 0, 0);

    // kick chunks 0,1
    #pragma unroll
    for (int s = 0; s < 2; s++) {
        const float4* src = (const float4*)(keys + ((size_t)bid * T_SZ + s * 50) * E_DIM);
        uint32_t stg = smb + OFF_STG + (s & 1) * STG_SZ;
        #pragma unroll
        for (int i = 0; i < 7; i++) {
            int idx = i * NTHR + tid;
            if (idx < 1600) cp16(stg + idx * 16, src + idx);
        }
        CP_COMMIT();
    }

    const uint32_t aB = smb + OFF_A + (lane & 15) * ROW_A + (lane >> 4) * 16;

    int j = 0;
    for (int b = bid; b < B_SZ; b += GRID, j++) {
        // B fragments (coalesced, L2-resident)
        uint32_t bf[4][8][2];
        {
            const uint4* wb4 = g_Wbf + ((size_t)b * 2 + ng) * 512 + lane;
            #pragma unroll
            for (int nt = 0; nt < 4; nt++)
                #pragma unroll
                for (int k2 = 0; k2 < 4; k2++) {
                    uint4 v = __ldg(&wb4[nt * 128 + k2 * 32]);
                    bf[nt][2 * k2][0] = v.x;     bf[nt][2 * k2][1] = v.y;
                    bf[nt][2 * k2 + 1][0] = v.z; bf[nt][2 * k2 + 1][1] = v.w;
                }
        }
        float qa[8];
        #pragma unroll
        for (int nt = 0; nt < 4; nt++) {
            qa[2 * nt]     = __ldg(&g_qA[(size_t)b * 64 + ng * 32 + nt * 8 + 2 * lr]);
            qa[2 * nt + 1] = __ldg(&g_qA[(size_t)b * 64 + ng * 32 + nt * 8 + 2 * lr + 1]);
        }

        // ---- 4 convert phases (self-mapped; cross-batch refill) ----
        #pragma unroll
        for (int c = 0; c < 4; c++) {
            const int s = 4 * j + c;
            CP_WAIT(1);
            const float4* s4 = (const float4*)(sm + OFF_STG + (s & 1) * STG_SZ);
            float4 v[7];
            #pragma unroll
            for (int i = 0; i < 7; i++) {
                int idx = i * NTHR + tid;
                if (idx < 1600) v[i] = s4[idx];
            }
            const int s2 = s + 2;
            if (s2 < nchunks) {
                int b2 = bid + (s2 >> 2) * GRID;
                const float4* src = (const float4*)(keys + ((size_t)b2 * T_SZ + (s2 & 3) * 50) * E_DIM);
                uint32_t stg = smb + OFF_STG + (s2 & 1) * STG_SZ;
                #pragma unroll
                for (int i = 0; i < 7; i++) {
                    int idx = i * NTHR + tid;
                    if (idx < 1600) cp16(stg + idx * 16, src + idx);
                }
            }
            CP_COMMIT();
            #pragma unroll
            for (int i = 0; i < 7; i++) {
                int idx = i * NTHR + tid;
                if (idx < 1600) {
                    int row = c * 50 + (idx >> 5), cc = idx & 31;
                    *(uint2*)(sm + OFF_A + row * ROW_A + cc * 8) =
                        make_uint2(pkf16(v[i].x, v[i].y), pkf16(v[i].z, v[i].w));
                }
            }
        }
        __syncthreads();                         // (S1) A ready

        // ---- per-tile mma + inline epilogue (acc reused per tile: no spills) ----
        #pragma unroll
        for (int i = 0; i < 4; i++) {
            int t = mg + 4 * i;
            if (t < 13) {
                float acc[4][4];
                #pragma unroll
                for (int nt = 0; nt < 4; nt++)
                    #pragma unroll
                    for (int u = 0; u < 4; u++) acc[nt][u] = 0.f;
                #pragma unroll
                for (int ks = 0; ks < 8; ks++) {
                    uint32_t a[4];
                    LDSM4(a, aB + t * (16 * ROW_A) + ks * 32);
                    #pragma unroll
                    for (int nt = 0; nt < 4; nt++)
                        mma_f16(acc[nt], a, bf[nt][ks][0], bf[nt][ks][1]);
                }
                float p0 = 0.f, p1 = 0.f;
                #pragma unroll
                for (int nt = 0; nt < 4; nt++) {
                    p0 += fmaxf(acc[nt][0] + qa[2 * nt],     0.f) * w1v[2 * nt]
                        + fmaxf(acc[nt][1] + qa[2 * nt + 1], 0.f) * w1v[2 * nt + 1];
                    p1 += fmaxf(acc[nt][2] + qa[2 * nt],     0.f) * w1v[2 * nt]
                        + fmaxf(acc[nt][3] + qa[2 * nt + 1], 0.f) * w1v[2 * nt + 1];
                }
                p0 += __shfl_xor_sync(0xffffffffu, p0, 1);
                p0 += __shfl_xor_sync(0xffffffffu, p0, 2);
                p1 += __shfl_xor_sync(0xffffffffu, p1, 1);
                p1 += __shfl_xor_sync(0xffffffffu, p1, 2);
                if (lr == 0) {
                    sRed[ng * 208 + t * 16 + lq]     = p0;
                    sRed[ng * 208 + t * 16 + lq + 8] = p1;
                }
            }
        }
        __syncthreads();                         // (S2) sRed ready
        if (tid < T_SZ)
            out[(size_t)b * T_SZ + tid] = sRed[tid] + sRed[208 + tid] + b1v;
        // next batch's S1 orders A/sRed reuse
    }
}

extern "C" void kernel_launch(void* const* d_in, const int* in_sizes, int n_in,
                              void* d_out, int out_size) {
    const float* query = (const float*)d_in[0];
    const float* keys  = (const float*)d_in[1];
    const float* W0    = (const float*)d_in[2];
    const float* b0    = (const float*)d_in[3];
    const float* W1    = (const float*)d_in[4];
    const float* b1    = (const float*)d_in[5];
    float* out = (float*)d_out;

    cudaFuncSetAttribute(lau_main, cudaFuncAttributeMaxDynamicSharedMemorySize, SMEM_BYTES);

    prep0<<<64, 256>>>(W0);
    prep1<<<B_SZ, 256>>>(query, b0);
    lau_main<<<GRID, NTHR, SMEM_BYTES>>>(keys, W1, b1, out);
}